// round 1
// baseline (speedup 1.0000x reference)
#include <cuda_runtime.h>
#include <math.h>

// Fused forward + VJP of the 4-layer VectorField.
// Per block: 32 rows, 256 threads. 12 smem-staged 128x128 GEMMs per block.
// Backward needs: softplus output a (xhat = (a-mu)*rstd; sigmoid(u) = 1-exp(-a)),
// LN mu/rstd per row per layer. All kept in shared memory — no global scratch.

#define NT    256
#define RT    32
#define PITCH 129
#define HN    128
#define LNUM  4
#define EPSF  1e-5f

// smem layout (floats): w[128*129] | buf[32*129] | act[4*32*129] | semb[4*128] | mu[4*32] | rs[4*32]
#define SMEM_FLOATS (128*PITCH + RT*PITCH + LNUM*RT*PITCH + LNUM*HN + 2*LNUM*RT)
#define SMEM_BYTES  (SMEM_FLOATS * 4)

__device__ __forceinline__ float reduce8(float v) {
    v += __shfl_xor_sync(0xffffffffu, v, 1, 8);
    v += __shfl_xor_sync(0xffffffffu, v, 2, 8);
    v += __shfl_xor_sync(0xffffffffu, v, 4, 8);
    return v;
}

// Load a 128x128 row-major weight into smem with pitch 129.
// TRANSPOSE=true  : ws[k*PITCH + j] = W[j,k]   (forward:  out_j = sum_k in_k W[j,k])
// TRANSPOSE=false : ws[j*PITCH + k] = W[j,k]   (backward: out_k = sum_j in_j W[j,k])
// Generic GEMM below always reads ws[kk*PITCH + jj] (kk = reduction index).
template<bool TRANSPOSE>
__device__ __forceinline__ void load_w(float* __restrict__ ws, const float* __restrict__ g) {
    #pragma unroll 4
    for (int idx = threadIdx.x; idx < HN * HN; idx += NT) {
        int j = idx >> 7, k = idx & 127;
        ws[TRANSPOSE ? (k * PITCH + j) : (j * PITCH + k)] = g[idx];
    }
}

// out[r][j] = sum_k A[r][k] * W[k][j]; thread (tx,ty) owns rows {ty+8rr}, cols {tx+32jj}.
__device__ __forceinline__ void gemm128(const float* __restrict__ A, const float* __restrict__ W,
                                        float acc[4][4], int tx, int ty) {
    #pragma unroll 4
    for (int k = 0; k < HN; ++k) {
        float a0 = A[(ty +  0) * PITCH + k];
        float a1 = A[(ty +  8) * PITCH + k];
        float a2 = A[(ty + 16) * PITCH + k];
        float a3 = A[(ty + 24) * PITCH + k];
        const float* wp = W + k * PITCH + tx;
        float w0 = wp[0], w1 = wp[32], w2 = wp[64], w3 = wp[96];
        acc[0][0] = fmaf(a0, w0, acc[0][0]); acc[0][1] = fmaf(a0, w1, acc[0][1]);
        acc[0][2] = fmaf(a0, w2, acc[0][2]); acc[0][3] = fmaf(a0, w3, acc[0][3]);
        acc[1][0] = fmaf(a1, w0, acc[1][0]); acc[1][1] = fmaf(a1, w1, acc[1][1]);
        acc[1][2] = fmaf(a1, w2, acc[1][2]); acc[1][3] = fmaf(a1, w3, acc[1][3]);
        acc[2][0] = fmaf(a2, w0, acc[2][0]); acc[2][1] = fmaf(a2, w1, acc[2][1]);
        acc[2][2] = fmaf(a2, w2, acc[2][2]); acc[2][3] = fmaf(a2, w3, acc[2][3]);
        acc[3][0] = fmaf(a3, w0, acc[3][0]); acc[3][1] = fmaf(a3, w1, acc[3][1]);
        acc[3][2] = fmaf(a3, w2, acc[3][2]); acc[3][3] = fmaf(a3, w3, acc[3][3]);
    }
}

__global__ void __launch_bounds__(NT, 1)
clnf_fused_kernel(const float* __restrict__ t,    const float* __restrict__ p,
                  const float* __restrict__ wct,
                  const float* __restrict__ W_in, const float* __restrict__ b_in,
                  const float* __restrict__ fw,   const float* __restrict__ fb,
                  const float* __restrict__ gamma,const float* __restrict__ beta,
                  const float* __restrict__ Wl,   const float* __restrict__ bl,
                  const float* __restrict__ W_out,const float* __restrict__ b_out,
                  float* __restrict__ out, int Btot)
{
    extern __shared__ float sm[];
    float* w_s  = sm;
    float* buf  = w_s  + 128 * PITCH;
    float* act  = buf  + RT * PITCH;
    float* semb = act  + LNUM * RT * PITCH;
    float* mu_s = semb + LNUM * HN;
    float* rs_s = mu_s + LNUM * RT;

    const int tid = threadIdx.x;
    const int tx = tid & 31, ty = tid >> 5;   // GEMM mapping
    const int er = tid >> 3;                  // elementwise: row 0..31
    const int ec = (tid & 7) * 16;            // elementwise: 16-col segment
    const size_t row0 = (size_t)blockIdx.x * RT;

    // time embedding s[i][j] = sin(t*fw + fb)
    const float tv = t[0];
    for (int i = tid; i < LNUM * HN; i += NT)
        semb[i] = sinf(tv * fw[i] + fb[i]);

    // load p tile
    for (int idx = tid; idx < RT * HN; idx += NT) {
        int r = idx >> 7, c = idx & 127;
        buf[r * PITCH + c] = p[(row0 + r) * HN + c];
    }

    // ======= FORWARD =======
    // h0 = p @ W_in^T + b_in
    load_w<true>(w_s, W_in);
    __syncthreads();
    {
        float acc[4][4] = {};
        gemm128(buf, w_s, acc, tx, ty);
        __syncthreads();
        #pragma unroll
        for (int rr = 0; rr < 4; ++rr)
            #pragma unroll
            for (int jj = 0; jj < 4; ++jj)
                buf[(ty + 8*rr) * PITCH + tx + 32*jj] = acc[rr][jj] + b_in[tx + 32*jj];
    }
    __syncthreads();

    for (int i = 0; i < LNUM; ++i) {
        // u = h + s_i; a = softplus(u); LN
        {
            float* hrow = buf + er * PITCH;
            float* arow = act + (i * RT + er) * PITCH;
            float sum = 0.f;
            #pragma unroll
            for (int c = 0; c < 16; ++c) {
                float u = hrow[ec + c] + semb[i * HN + ec + c];
                float a = fmaxf(u, 0.f) + log1pf(expf(-fabsf(u)));
                arow[ec + c] = a;
                sum += a;
            }
            float mu = reduce8(sum) * (1.f / HN);
            float vs = 0.f;
            #pragma unroll
            for (int c = 0; c < 16; ++c) { float d = arow[ec + c] - mu; vs += d * d; }
            float rstd = rsqrtf(reduce8(vs) * (1.f / HN) + EPSF);
            if ((tid & 7) == 0) { mu_s[i * RT + er] = mu; rs_s[i * RT + er] = rstd; }
            #pragma unroll
            for (int c = 0; c < 16; ++c) {
                float xh = (arow[ec + c] - mu) * rstd;
                hrow[ec + c] = xh * gamma[i * HN + ec + c] + beta[i * HN + ec + c];
            }
        }
        __syncthreads();
        load_w<true>(w_s, Wl + i * HN * HN);
        __syncthreads();
        {
            float acc[4][4] = {};
            gemm128(buf, w_s, acc, tx, ty);
            __syncthreads();
            #pragma unroll
            for (int rr = 0; rr < 4; ++rr)
                #pragma unroll
                for (int jj = 0; jj < 4; ++jj)
                    buf[(ty + 8*rr) * PITCH + tx + 32*jj] = acc[rr][jj] + bl[i * HN + tx + 32*jj];
        }
        __syncthreads();
    }

    // dp = h @ W_out^T + b_out  (written straight to global)
    load_w<true>(w_s, W_out);
    __syncthreads();
    {
        float acc[4][4] = {};
        gemm128(buf, w_s, acc, tx, ty);
        #pragma unroll
        for (int rr = 0; rr < 4; ++rr)
            #pragma unroll
            for (int jj = 0; jj < 4; ++jj)
                out[(row0 + ty + 8*rr) * HN + tx + 32*jj] = acc[rr][jj] + b_out[tx + 32*jj];
    }
    __syncthreads();

    // ======= BACKWARD =======
    // g = w @ W_out  (cotangent through output matmul)
    for (int idx = tid; idx < RT * HN; idx += NT) {
        int r = idx >> 7, c = idx & 127;
        buf[r * PITCH + c] = wct[(row0 + r) * HN + c];
    }
    load_w<false>(w_s, W_out);
    __syncthreads();
    {
        float acc[4][4] = {};
        gemm128(buf, w_s, acc, tx, ty);
        __syncthreads();
        #pragma unroll
        for (int rr = 0; rr < 4; ++rr)
            #pragma unroll
            for (int jj = 0; jj < 4; ++jj)
                buf[(ty + 8*rr) * PITCH + tx + 32*jj] = acc[rr][jj];
    }
    __syncthreads();

    for (int i = LNUM - 1; i >= 0; --i) {
        // g_y = g @ Wl[i]
        load_w<false>(w_s, Wl + i * HN * HN);
        __syncthreads();
        {
            float acc[4][4] = {};
            gemm128(buf, w_s, acc, tx, ty);
            __syncthreads();
            #pragma unroll
            for (int rr = 0; rr < 4; ++rr)
                #pragma unroll
                for (int jj = 0; jj < 4; ++jj)
                    buf[(ty + 8*rr) * PITCH + tx + 32*jj] = acc[rr][jj];
        }
        __syncthreads();
        // LN backward + softplus backward
        {
            const float mu   = mu_s[i * RT + er];
            const float rstd = rs_s[i * RT + er];
            float* grow = buf + er * PITCH;
            const float* arow = act + (i * RT + er) * PITCH;
            float gg[16], xh[16];
            float s1 = 0.f, s2 = 0.f;
            #pragma unroll
            for (int c = 0; c < 16; ++c) {
                float a = arow[ec + c];
                float x = (a - mu) * rstd;
                float g = grow[ec + c] * gamma[i * HN + ec + c];
                gg[c] = g; xh[c] = x;
                s1 += g; s2 += g * x;
            }
            s1 = reduce8(s1) * (1.f / HN);
            s2 = reduce8(s2) * (1.f / HN);
            #pragma unroll
            for (int c = 0; c < 16; ++c) {
                float ga = rstd * (gg[c] - s1 - xh[c] * s2);
                float sg = 1.f - expf(-arow[ec + c]);   // sigmoid(u) from a = softplus(u)
                grow[ec + c] = ga * sg;
            }
        }
        __syncthreads();
    }

    // dw = -(g @ W_in)
    load_w<false>(w_s, W_in);
    __syncthreads();
    {
        float acc[4][4] = {};
        gemm128(buf, w_s, acc, tx, ty);
        float* dw = out + (size_t)Btot * HN;
        #pragma unroll
        for (int rr = 0; rr < 4; ++rr)
            #pragma unroll
            for (int jj = 0; jj < 4; ++jj)
                dw[(row0 + ty + 8*rr) * HN + tx + 32*jj] = -acc[rr][jj];
    }
}

extern "C" void kernel_launch(void* const* d_in, const int* in_sizes, int n_in,
                              void* d_out, int out_size) {
    const float* t     = (const float*)d_in[0];
    const float* p     = (const float*)d_in[1];
    const float* w     = (const float*)d_in[2];
    const float* W_in  = (const float*)d_in[3];
    const float* b_in  = (const float*)d_in[4];
    const float* fw    = (const float*)d_in[5];
    const float* fb    = (const float*)d_in[6];
    const float* gamma = (const float*)d_in[7];
    const float* beta  = (const float*)d_in[8];
    const float* Wl    = (const float*)d_in[9];
    const float* bl    = (const float*)d_in[10];
    const float* W_out = (const float*)d_in[11];
    const float* b_out = (const float*)d_in[12];
    float* out = (float*)d_out;

    int Btot = in_sizes[1] / HN;   // 131072

    cudaFuncSetAttribute(clnf_fused_kernel,
                         cudaFuncAttributeMaxDynamicSharedMemorySize, SMEM_BYTES);
    clnf_fused_kernel<<<Btot / RT, NT, SMEM_BYTES>>>(
        t, p, w, W_in, b_in, fw, fb, gamma, beta, Wl, bl, W_out, b_out, out, Btot);
}

// round 6
// speedup vs baseline: 2.2598x; 2.2598x over previous
#include <cuda_runtime.h>
#include <cuda_bf16.h>
#include <cstdint>
#include <math.h>

// Fused forward+VJP via base-ISA mma.sync (bf16 HMMA), split hi/lo 3-term for accuracy.
// CTA = 128 rows, 8 warps; warp owns a 16x128 stripe. Activation chain lives in
// mma fragments (accumulator layout == next A-fragment layout). Weights staged in
// smem (hi/lo bf16, pitch 136 halves) and read via ldmatrix. Softplus activations
// for backward stored to __device__ scratch in a lane-coalesced layout.

#define NT    256
#define HN    128
#define LNUM  4
#define MCTA  128
#define BTOT  131072
#define EPSF  1e-5f
#define PW    136            // smem weight pitch in halves (272B rows: conflict-free ldmatrix)

__device__ float g_act[(size_t)LNUM * BTOT * HN];   // 256MB scratch

// ---- smem byte offsets ----
#define WHI_OFF   0u
#define WLO_OFF   34816u              // 128*136*2
#define SEMB_OFF  69632u              // 512 floats
#define SGAM_OFF  71680u
#define SBET_OFF  73728u
#define SBIA_OFF  75776u              // 768 floats: [b_in | bl0..bl3 | b_out]
#define SMEM_BYTES 78848u

__device__ __forceinline__ uint32_t s2u(const void* p) {
    uint32_t a;
    asm("{ .reg .u64 t; cvta.to.shared.u64 t, %1; cvt.u32.u64 %0, t; }" : "=r"(a) : "l"(p));
    return a;
}

#define LDSM4(b0,b1,b2,b3, addr) \
    asm volatile("ldmatrix.sync.aligned.m8n8.x4.shared.b16 {%0,%1,%2,%3}, [%4];" \
        : "=r"(b0),"=r"(b1),"=r"(b2),"=r"(b3) : "r"(addr))

#define MMA(c, a, b0, b1) \
    asm volatile("mma.sync.aligned.m16n8k16.row.col.f32.bf16.bf16.f32 " \
        "{%0,%1,%2,%3},{%4,%5,%6,%7},{%8,%9},{%0,%1,%2,%3};" \
        : "+f"((c)[0]),"+f"((c)[1]),"+f"((c)[2]),"+f"((c)[3]) \
        : "r"((a)[0]),"r"((a)[1]),"r"((a)[2]),"r"((a)[3]), "r"(b0),"r"(b1))

#define QUADSUM(v) do { \
    v += __shfl_xor_sync(0xffffffffu, v, 1); \
    v += __shfl_xor_sync(0xffffffffu, v, 2); } while (0)

__device__ __forceinline__ void split2(float x, float y, uint32_t& hi, uint32_t& lo) {
    __nv_bfloat16 hx = __float2bfloat16_rn(x), hy = __float2bfloat16_rn(y);
    float lx = x - __bfloat162float(hx), ly = y - __bfloat162float(hy);
    __nv_bfloat162 H; H.x = hx; H.y = hy;
    __nv_bfloat162 L; L.x = __float2bfloat16_rn(lx); L.y = __float2bfloat16_rn(ly);
    hi = *reinterpret_cast<uint32_t*>(&H);
    lo = *reinterpret_cast<uint32_t*>(&L);
}

__device__ __forceinline__ float softplusf(float u) {
    return fmaxf(u, 0.f) + log1pf(expf(-fabsf(u)));
}

__global__ void __launch_bounds__(NT, 1)
clnf_mma_kernel(const float* __restrict__ t,    const float* __restrict__ p,
                const float* __restrict__ wct,
                const float* __restrict__ W_in, const float* __restrict__ b_in,
                const float* __restrict__ fw,   const float* __restrict__ fb,
                const float* __restrict__ gamma,const float* __restrict__ beta,
                const float* __restrict__ Wl,   const float* __restrict__ bl,
                const float* __restrict__ W_out,const float* __restrict__ b_out,
                float* __restrict__ out, int Btot)
{
    extern __shared__ char sm[];
    const uint32_t smu = s2u(sm);
    float* semb = (float*)(sm + SEMB_OFF);
    float* sgam = (float*)(sm + SGAM_OFF);
    float* sbet = (float*)(sm + SBET_OFF);
    float* sbia = (float*)(sm + SBIA_OFF);

    const int tid  = threadIdx.x;
    const int wid  = tid >> 5;
    const int lane = tid & 31;
    const int qr   = lane >> 2;          // 0..7  fragment row group
    const int col0 = (lane & 3) * 2;     // fragment column pair base

    // ldmatrix per-lane byte offset within a weight tile
    const uint32_t laneOff = (uint32_t)(((lane & 7) + ((lane >> 4) << 3)) * (PW * 2)
                                        + (((lane >> 3) & 1) * 8) * 2);
    const uint32_t whiu = smu + WHI_OFF;
    const uint32_t wlou = smu + WLO_OFF;

    // ---- stage constants ----
    {
        const float tv = t[0];
        for (int i = tid; i < LNUM * HN; i += NT) {
            semb[i] = sinf(tv * fw[i] + fb[i]);
            sgam[i] = gamma[i];
            sbet[i] = beta[i];
        }
        for (int i = tid; i < 768; i += NT) {
            float v;
            if (i < 128)      v = b_in[i];
            else if (i < 640) v = bl[i - 128];
            else              v = b_out[i - 640];
            sbia[i] = v;
        }
    }

    // persistent register state
    float    acc[16][4];
    uint32_t ahi[32], alo[32];
    float muA[LNUM][2], rsA[LNUM][2];

    const size_t rowg0 = (size_t)blockIdx.x * MCTA + wid * 16 + qr;  // global row (frag row0)
    float* actB = g_act + ((size_t)((blockIdx.x * 8 + wid) * LNUM)) * 2048 + lane;

    // ---- stage a 128x128 weight into smem as hi/lo bf16, pitch PW ----
    auto stageW = [&](const float* __restrict__ W, bool transp) {
        __syncthreads();
        const float2* W2 = reinterpret_cast<const float2*>(W);
        __nv_bfloat16* wh = (__nv_bfloat16*)(sm + WHI_OFF);
        __nv_bfloat16* wl = (__nv_bfloat16*)(sm + WLO_OFF);
        #pragma unroll 4
        for (int idx = tid; idx < HN * HN / 2; idx += NT) {
            int j  = idx >> 6;
            int k2 = (idx & 63) * 2;
            float2 v = __ldg(&W2[idx]);
            __nv_bfloat16 h0 = __float2bfloat16_rn(v.x);
            __nv_bfloat16 h1 = __float2bfloat16_rn(v.y);
            __nv_bfloat16 l0 = __float2bfloat16_rn(v.x - __bfloat162float(h0));
            __nv_bfloat16 l1 = __float2bfloat16_rn(v.y - __bfloat162float(h1));
            if (!transp) {
                int o = j * PW + k2;
                wh[o] = h0; wh[o + 1] = h1;
                wl[o] = l0; wl[o + 1] = l1;
            } else {
                int o0 = k2 * PW + j, o1 = (k2 + 1) * PW + j;
                wh[o0] = h0; wh[o1] = h1;
                wl[o0] = l0; wl[o1] = l1;
            }
        }
        __syncthreads();
    };

    // ---- GEMM: acc[16][4] = (Ahi+Alo) x (Whi) + Ahi x (Wlo), A from frag regs ----
    auto gemm = [&]() {
        #pragma unroll
        for (int n = 0; n < 16; ++n)
            #pragma unroll
            for (int j = 0; j < 4; ++j) acc[n][j] = 0.f;
        #pragma unroll
        for (int kk = 0; kk < 8; ++kk) {
            const uint32_t* A = ahi + kk * 4;
            const uint32_t* L = alo + kk * 4;
            #pragma unroll
            for (int np = 0; np < 8; ++np) {
                uint32_t toff = (uint32_t)(np * (16 * PW * 2) + kk * 32);
                uint32_t h0, h1, h2, h3;
                LDSM4(h0, h1, h2, h3, whiu + laneOff + toff);
                MMA(acc[2 * np],     A, h0, h1);
                MMA(acc[2 * np + 1], A, h2, h3);
                MMA(acc[2 * np],     L, h0, h1);
                MMA(acc[2 * np + 1], L, h2, h3);
                uint32_t l0, l1, l2, l3;
                LDSM4(l0, l1, l2, l3, wlou + laneOff + toff);
                MMA(acc[2 * np],     A, l0, l1);
                MMA(acc[2 * np + 1], A, l2, l3);
            }
        }
    };

    // ---- load A fragments (hi/lo) straight from a global [rows x 128] matrix ----
    auto loadA = [&](const float* __restrict__ src) {
        const float* S0 = src + rowg0 * HN;
        const float* S1 = S0 + 8 * HN;
        #pragma unroll
        for (int kk = 0; kk < 8; ++kk) {
            int c = kk * 16 + col0;
            float2 v00 = *(const float2*)(S0 + c);
            float2 v01 = *(const float2*)(S0 + c + 8);
            float2 v10 = *(const float2*)(S1 + c);
            float2 v11 = *(const float2*)(S1 + c + 8);
            split2(v00.x, v00.y, ahi[kk * 4 + 0], alo[kk * 4 + 0]);
            split2(v10.x, v10.y, ahi[kk * 4 + 1], alo[kk * 4 + 1]);
            split2(v01.x, v01.y, ahi[kk * 4 + 2], alo[kk * 4 + 2]);
            split2(v11.x, v11.y, ahi[kk * 4 + 3], alo[kk * 4 + 3]);
        }
    };

    // ================= FORWARD =================
    loadA(p);
    stageW(W_in, false);
    gemm();                                     // acc = p @ W_in^T

    #pragma unroll
    for (int i = 0; i < LNUM; ++i) {
        const float* bias = sbia + i * 128;     // b_in (i=0) or bl[i-1]
        const float* se   = semb + i * 128;
        float s0 = 0.f, q0 = 0.f, s1 = 0.f, q1 = 0.f;
        #pragma unroll
        for (int n = 0; n < 16; ++n) {
            int c = n * 8 + col0;
            float2 bb = *(const float2*)(bias + c);
            float2 ss = *(const float2*)(se + c);
            float a00 = softplusf(acc[n][0] + bb.x + ss.x);
            float a01 = softplusf(acc[n][1] + bb.y + ss.y);
            float a10 = softplusf(acc[n][2] + bb.x + ss.x);
            float a11 = softplusf(acc[n][3] + bb.y + ss.y);
            acc[n][0] = a00; acc[n][1] = a01; acc[n][2] = a10; acc[n][3] = a11;
            s0 += a00 + a01; q0 += a00 * a00 + a01 * a01;
            s1 += a10 + a11; q1 += a10 * a10 + a11 * a11;
        }
        QUADSUM(s0); QUADSUM(q0); QUADSUM(s1); QUADSUM(q1);
        float mu0 = s0 * (1.f / HN), mu1 = s1 * (1.f / HN);
        float rs0 = rsqrtf(q0 * (1.f / HN) - mu0 * mu0 + EPSF);
        float rs1 = rsqrtf(q1 * (1.f / HN) - mu1 * mu1 + EPSF);
        muA[i][0] = mu0; muA[i][1] = mu1; rsA[i][0] = rs0; rsA[i][1] = rs1;
        float* ap = actB + (size_t)i * 2048;
        #pragma unroll
        for (int n = 0; n < 16; ++n) {
            ap[(n * 4 + 0) * 32] = acc[n][0];
            ap[(n * 4 + 1) * 32] = acc[n][1];
            ap[(n * 4 + 2) * 32] = acc[n][2];
            ap[(n * 4 + 3) * 32] = acc[n][3];
        }
        const float* gmp = sgam + i * 128;
        const float* btp = sbet + i * 128;
        #pragma unroll
        for (int n = 0; n < 16; ++n) {
            int c = n * 8 + col0;
            float2 g2 = *(const float2*)(gmp + c);
            float2 b2 = *(const float2*)(btp + c);
            float y00 = (acc[n][0] - mu0) * rs0 * g2.x + b2.x;
            float y01 = (acc[n][1] - mu0) * rs0 * g2.y + b2.y;
            float y10 = (acc[n][2] - mu1) * rs1 * g2.x + b2.x;
            float y11 = (acc[n][3] - mu1) * rs1 * g2.y + b2.y;
            int base = (n >> 1) * 4 + (n & 1) * 2;
            split2(y00, y01, ahi[base],     alo[base]);
            split2(y10, y11, ahi[base + 1], alo[base + 1]);
        }
        stageW(Wl + (size_t)i * HN * HN, false);
        gemm();                                 // acc = y_i @ Wl_i^T
    }

    // h4 = acc + bl[3] -> fragments
    {
        const float* bias = sbia + 4 * 128;     // bl[3]
        #pragma unroll
        for (int n = 0; n < 16; ++n) {
            int c = n * 8 + col0;
            float2 bb = *(const float2*)(bias + c);
            int base = (n >> 1) * 4 + (n & 1) * 2;
            split2(acc[n][0] + bb.x, acc[n][1] + bb.y, ahi[base],     alo[base]);
            split2(acc[n][2] + bb.x, acc[n][3] + bb.y, ahi[base + 1], alo[base + 1]);
        }
    }
    stageW(W_out, false);
    gemm();                                     // acc = h4 @ W_out^T

    // dp = acc + b_out
    {
        const float* bo = sbia + 640;
        float* O0 = out + rowg0 * HN;
        float* O1 = O0 + 8 * HN;
        #pragma unroll
        for (int n = 0; n < 16; ++n) {
            int c = n * 8 + col0;
            float2 bb = *(const float2*)(bo + c);
            float2 v0; v0.x = acc[n][0] + bb.x; v0.y = acc[n][1] + bb.y;
            float2 v1; v1.x = acc[n][2] + bb.x; v1.y = acc[n][3] + bb.y;
            *(float2*)(O0 + c) = v0;
            *(float2*)(O1 + c) = v1;
        }
    }

    // ================= BACKWARD =================
    loadA(wct);
    stageW(W_out, true);
    gemm();                                     // acc = w @ W_out  (g_h4)

    #pragma unroll
    for (int i = LNUM - 1; i >= 0; --i) {
        // fragments for g already in ahi/alo? No: acc holds g; convert now
        #pragma unroll
        for (int n = 0; n < 16; ++n) {
            int base = (n >> 1) * 4 + (n & 1) * 2;
            split2(acc[n][0], acc[n][1], ahi[base],     alo[base]);
            split2(acc[n][2], acc[n][3], ahi[base + 1], alo[base + 1]);
        }
        stageW(Wl + (size_t)i * HN * HN, true);
        gemm();                                 // acc = g @ Wl_i  (g_y)

        const float mu0 = muA[i][0], mu1 = muA[i][1];
        const float rs0 = rsA[i][0], rs1 = rsA[i][1];
        const float* gmp = sgam + i * 128;
        const float* ap = actB + (size_t)i * 2048;
        float s_0 = 0.f, t_0 = 0.f, s_1 = 0.f, t_1 = 0.f;
        #pragma unroll
        for (int n = 0; n < 16; ++n) {
            int c = n * 8 + col0;
            float2 g2 = *(const float2*)(gmp + c);
            float a00 = ap[(n * 4 + 0) * 32], a01 = ap[(n * 4 + 1) * 32];
            float a10 = ap[(n * 4 + 2) * 32], a11 = ap[(n * 4 + 3) * 32];
            float gg00 = acc[n][0] * g2.x, gg01 = acc[n][1] * g2.y;
            float gg10 = acc[n][2] * g2.x, gg11 = acc[n][3] * g2.y;
            s_0 += gg00 + gg01;
            t_0 += gg00 * (a00 - mu0) * rs0 + gg01 * (a01 - mu0) * rs0;
            s_1 += gg10 + gg11;
            t_1 += gg10 * (a10 - mu1) * rs1 + gg11 * (a11 - mu1) * rs1;
        }
        QUADSUM(s_0); QUADSUM(t_0); QUADSUM(s_1); QUADSUM(t_1);
        s_0 *= (1.f / HN); t_0 *= (1.f / HN);
        s_1 *= (1.f / HN); t_1 *= (1.f / HN);
        #pragma unroll
        for (int n = 0; n < 16; ++n) {
            int c = n * 8 + col0;
            float2 g2 = *(const float2*)(gmp + c);
            float a00 = ap[(n * 4 + 0) * 32], a01 = ap[(n * 4 + 1) * 32];
            float a10 = ap[(n * 4 + 2) * 32], a11 = ap[(n * 4 + 3) * 32];
            float xh00 = (a00 - mu0) * rs0, xh01 = (a01 - mu0) * rs0;
            float xh10 = (a10 - mu1) * rs1, xh11 = (a11 - mu1) * rs1;
            acc[n][0] = rs0 * (acc[n][0] * g2.x - s_0 - xh00 * t_0) * (1.f - expf(-a00));
            acc[n][1] = rs0 * (acc[n][1] * g2.y - s_0 - xh01 * t_0) * (1.f - expf(-a01));
            acc[n][2] = rs1 * (acc[n][2] * g2.x - s_1 - xh10 * t_1) * (1.f - expf(-a10));
            acc[n][3] = rs1 * (acc[n][3] * g2.y - s_1 - xh11 * t_1) * (1.f - expf(-a11));
        }
    }

    // fragments for g_h0, then dw = -(g_h0 @ W_in)
    #pragma unroll
    for (int n = 0; n < 16; ++n) {
        int base = (n >> 1) * 4 + (n & 1) * 2;
        split2(acc[n][0], acc[n][1], ahi[base],     alo[base]);
        split2(acc[n][2], acc[n][3], ahi[base + 1], alo[base + 1]);
    }
    stageW(W_in, true);
    gemm();

    {
        float* D0 = out + (size_t)Btot * HN + rowg0 * HN;
        float* D1 = D0 + 8 * HN;
        #pragma unroll
        for (int n = 0; n < 16; ++n) {
            int c = n * 8 + col0;
            float2 v0; v0.x = -acc[n][0]; v0.y = -acc[n][1];
            float2 v1; v1.x = -acc[n][2]; v1.y = -acc[n][3];
            *(float2*)(D0 + c) = v0;
            *(float2*)(D1 + c) = v1;
        }
    }
}

extern "C" void kernel_launch(void* const* d_in, const int* in_sizes, int n_in,
                              void* d_out, int out_size) {
    const float* t     = (const float*)d_in[0];
    const float* p     = (const float*)d_in[1];
    const float* w     = (const float*)d_in[2];
    const float* W_in  = (const float*)d_in[3];
    const float* b_in  = (const float*)d_in[4];
    const float* fw    = (const float*)d_in[5];
    const float* fb    = (const float*)d_in[6];
    const float* gamma = (const float*)d_in[7];
    const float* beta  = (const float*)d_in[8];
    const float* Wl    = (const float*)d_in[9];
    const float* bl    = (const float*)d_in[10];
    const float* W_out = (const float*)d_in[11];
    const float* b_out = (const float*)d_in[12];
    float* out = (float*)d_out;

    int Btot = in_sizes[1] / HN;   // 131072

    cudaFuncSetAttribute(clnf_mma_kernel,
                         cudaFuncAttributeMaxDynamicSharedMemorySize, SMEM_BYTES);
    clnf_mma_kernel<<<Btot / MCTA, NT, SMEM_BYTES>>>(
        t, p, w, W_in, b_in, fw, fb, gamma, beta, Wl, bl, W_out, b_out, out, Btot);
}